// round 12
// baseline (speedup 1.0000x reference)
#include <cuda_runtime.h>
#include <cooperative_groups.h>
namespace cg = cooperative_groups;

#define Bn 8
#define Nn 2048
#define Mn 256
#define Qn 16384
#define Dn 32
#define Kn 16
#define Hn 64
#define LAMf 5.0f
#define CG_ITERS 20

#define CLUSTER_ARRIVE() asm volatile("barrier.cluster.arrive.aligned;" ::: "memory")
#define CLUSTER_WAIT() asm volatile("barrier.cluster.wait.aligned;" ::: "memory")

__device__ float g_gvec[Bn * Dn];
__device__ float g_c0s[Bn * Mn * Dn];
__device__ float g_cs[Bn * Mn * Dn];

__device__ __forceinline__ float dot4(float4 a, float4 b) {
    return a.x * b.x + a.y * b.y + a.z * b.z + a.w * b.w;
}
__device__ __forceinline__ unsigned smem_u32(const void* p) {
    return (unsigned)__cvta_generic_to_shared(p);
}
__device__ __forceinline__ void mbar_init(unsigned a, unsigned c) {
    asm volatile("mbarrier.init.shared.b64 [%0], %1;" ::"r"(a), "r"(c) : "memory");
}
__device__ __forceinline__ void mbar_arrive_remote(unsigned local_addr, unsigned rank) {
    asm volatile(
        "{\n\t.reg .b32 ra;\n\t"
        "mapa.shared::cluster.u32 ra, %0, %1;\n\t"
        "mbarrier.arrive.release.cluster.shared::cluster.b64 _, [ra];\n\t}" ::"r"(local_addr),
        "r"(rank)
        : "memory");
}
__device__ __forceinline__ void mbar_wait(unsigned a, unsigned parity) {
    asm volatile(
        "{\n\t.reg .pred P;\n\tWL_%=:\n\t"
        "mbarrier.try_wait.parity.acquire.cluster.shared::cta.b64 P, [%0], %1;\n\t"
        "@P bra WD_%=;\n\tbra WL_%=;\n\tWD_%=:\n\t}" ::"r"(a),
        "r"(parity)
        : "memory");
}

// ---------------- k_g ----------------
__global__ __launch_bounds__(256) void k_g(const float* __restrict__ xs,
                                           const float* __restrict__ us,
                                           const float* __restrict__ Wg1,
                                           const float* __restrict__ bg1,
                                           const float* __restrict__ Wg2,
                                           const float* __restrict__ bg2) {
    __shared__ float part[256];
    __shared__ float gmean[Hn];
    int b = blockIdx.x, t = threadIdx.x;
    int h = t & 63, grp = t >> 6;
    float w0 = Wg1[h], w1 = Wg1[Hn + h], bb = bg1[h];
    float acc = 0.f;
    for (int n = grp; n < Nn; n += 4) {
        float v = fmaf(xs[b * Nn + n], w0, fmaf(us[b * Nn + n], w1, bb));
        acc += fmaxf(v, 0.f);
    }
    part[t] = acc;
    __syncthreads();
    if (t < Hn)
        gmean[t] = (part[t] + part[t + 64] + part[t + 128] + part[t + 192]) * (1.0f / (float)Nn);
    __syncthreads();
    if (t < Dn) {
        float a = bg2[t];
#pragma unroll
        for (int hh = 0; hh < Hn; hh++) a = fmaf(gmean[hh], Wg2[hh * Dn + t], a);
        g_gvec[b * Dn + t] = a;
    }
}

// ---------------- encoder (4 m / block) ----------------
__global__ __launch_bounds__(256) void k_encode(const float* __restrict__ xs,
                                                const float* __restrict__ us,
                                                const float* __restrict__ centers,
                                                const float* __restrict__ W1,
                                                const float* __restrict__ b1,
                                                const float* __restrict__ W2,
                                                const float* __restrict__ b2,
                                                const float* __restrict__ W3,
                                                const float* __restrict__ b3,
                                                const int* __restrict__ idx,
                                                float* __restrict__ out_c0) {
    __shared__ float W2s[Hn * Hn];
    __shared__ float h1[4][Kn][Hn];
    __shared__ float sx[4][Kn], su[4][Kn];
    __shared__ float hm[4][Hn];
    int blk = blockIdx.x;
    int b = blk >> 6, mbase = (blk & 63) << 2;
    int t = threadIdx.x, gr = t >> 6, h = t & 63;

    for (int i = t; i < Hn * Hn; i += 256) W2s[i] = W2[i];
    if (t < 64) {
        int gr2 = t >> 4, k = t & 15;
        int id = idx[(mbase + gr2) * Kn + k];
        sx[gr2][k] = xs[b * Nn + id];
        su[gr2][k] = us[b * Nn + id];
    }
    __syncthreads();
    int m = mbase + gr;
    const float invR = (float)Mn / 1.5f;
    float w1a = W1[h], w1b = W1[Hn + h], bb1 = b1[h];
    float cm = centers[m];
#pragma unroll
    for (int k = 0; k < Kn; k++) {
        float rel = (sx[gr][k] - cm) * invR;
        h1[gr][k][h] = fmaxf(fmaf(rel, w1a, fmaf(su[gr][k], w1b, bb1)), 0.f);
    }
    __syncthreads();
    float bb2 = b2[h];
    float accv[Kn];
#pragma unroll
    for (int k = 0; k < Kn; k++) accv[k] = bb2;
#pragma unroll
    for (int hh = 0; hh < Hn; hh += 4) {
        float wa = W2s[(hh + 0) * Hn + h], wb = W2s[(hh + 1) * Hn + h];
        float wc = W2s[(hh + 2) * Hn + h], wd = W2s[(hh + 3) * Hn + h];
#pragma unroll
        for (int k = 0; k < Kn; k++) {
            float4 hv = *(const float4*)&h1[gr][k][hh];
            accv[k] = fmaf(hv.x, wa, accv[k]);
            accv[k] = fmaf(hv.y, wb, accv[k]);
            accv[k] = fmaf(hv.z, wc, accv[k]);
            accv[k] = fmaf(hv.w, wd, accv[k]);
        }
    }
    float ssum = 0.f;
#pragma unroll
    for (int k = 0; k < Kn; k++) ssum += fmaxf(accv[k], 0.f);
    hm[gr][h] = ssum * (1.0f / (float)Kn);
    __syncthreads();
    if (h < Dn) {
        float a = b3[h];
#pragma unroll
        for (int hh = 0; hh < Hn; hh++) a = fmaf(hm[gr][hh], W3[hh * Dn + h], a);
        a += g_gvec[b * Dn + h];
        int gi = (b * Mn + m) * Dn + h;
        g_c0s[gi] = a;
        out_c0[gi] = a;
    }
}

// ==================== pipelined CG: 4 clusters x 8 CTAs, 2 batches ====================
// t = m*16 + dq*2 + b
#define OFF_RS 0
#define OFF_RD 16896
#define OFF_W 33792     // [2][34][32]
#define OFF_RE 35968    // [2][33][16]
#define OFF_REDA 37024  // [2][16]
#define OFF_REDB 37056  // [2][16]
#define OFF_SLOT 37088  // [2 par][4][8]
#define OFF_STGL 37152  // [2 par][2 b][32]
#define OFF_STGR 37280
#define OFF_MBAR 37408  // 2 x u64
#define CG_SM_FLOATS 37412

__global__ void __cluster_dims__(8, 1, 1) __launch_bounds__(512, 1)
    k_cg(const float* __restrict__ Rsrc, const float* __restrict__ Rdst,
         float* __restrict__ out_c) {
    extern __shared__ float smf[];
    float4* Rs4 = (float4*)(smf + OFF_RS);
    float4* Rd4 = (float4*)(smf + OFF_RD);
    float4* w4s = (float4*)(smf + OFF_W);
    float* re_sm = smf + OFF_RE;
    float* redA = smf + OFF_REDA;
    float* redB = smf + OFF_REDB;
    float* slots = smf + OFF_SLOT;
    float4* stgL = (float4*)(smf + OFF_STGL);
    float4* stgR = (float4*)(smf + OFF_STGR);

    cg::cluster_group cl = cg::this_cluster();
    const int t = threadIdx.x;
    const int l = t & 31, wp = t >> 5;
    const int c = blockIdx.x >> 3;
    const int s = blockIdx.x & 7;
    const int m = t >> 4;
    const int dq = (t >> 1) & 7;
    const int b = t & 1;
    const float4 z4 = make_float4(0.f, 0.f, 0.f, 0.f);
    const unsigned mbarL = smem_u32(smf + OFF_MBAR);
    const unsigned mbarR = mbarL + 8;

    if (t == 0) { mbar_init(mbarL, 1); mbar_init(mbarR, 1); }

    const float4* Rsg = (const float4*)Rsrc;
    const float4* Rdg = (const float4*)Rdst;
    for (int i4 = t; i4 < 33 * 128; i4 += 512) {
        int le = i4 >> 7, rem = i4 & 127;
        int ge = s * 32 - 1 + le;
        bool ok = (ge >= 0) && (ge < Mn - 1);
        Rs4[i4] = ok ? Rsg[ge * 128 + rem] : z4;
        Rd4[i4] = ok ? Rdg[ge * 128 + rem] : z4;
    }
    const float4* c0g = (const float4*)g_c0s;
    for (int i4 = t; i4 < 544; i4 += 512) {
        int bb = (i4 >= 272) ? 1 : 0;
        int rem = i4 - bb * 272;
        int slot = rem >> 3, j = rem & 7;
        int gm = s * 32 - 1 + slot;
        w4s[i4] = (gm >= 0 && gm < Mn) ? c0g[((c * 2 + bb) * Mn + gm) * 8 + j] : z4;
    }
    __syncthreads();

    float4 x4, r4, w4, q4, p4 = z4, s4 = z4, zv4 = z4;
    float g_old[2], a_old[2];

    // matvec: q4 = A w  (w in w4s ext + w4 reg for own)
    auto matvec = [&](int it) {
        if (it > 0) {
            unsigned par2 = (unsigned)((it - 1) & 1);
            if (t < 16) {
                if (s > 0) {
                    mbar_wait(mbarL, par2);
                    w4s[b * 272 + dq] = stgL[par2 * 16 + b * 8 + dq];
                }
            } else if (t < 32) {
                if (s < 7) {
                    mbar_wait(mbarR, par2);
                    w4s[b * 272 + 33 * 8 + dq] = stgR[par2 * 16 + b * 8 + dq];
                }
            }
        }
        __syncthreads();
        {
            int le = m;
            float4 p0 = w4s[b * 272 + le * 8 + dq];
            float4 p1 = w4s[b * 272 + le * 8 + 8 + dq];
            const float4* rsrow = Rs4 + le * 128 + dq;
            const float4* rdrow = Rd4 + le * 128 + dq;
#pragma unroll
            for (int rho = 0; rho < 16; rho++) {
                float a = dot4(rsrow[rho * 8], p0) - dot4(rdrow[rho * 8], p1);
                a += __shfl_xor_sync(0xffffffffu, a, 2);
                a += __shfl_xor_sync(0xffffffffu, a, 4);
                a += __shfl_xor_sync(0xffffffffu, a, 8);
                if ((t & 14) == 0) re_sm[b * 528 + le * 16 + rho] = a;
            }
        }
        if (wp < 8) {
            int rho = m;
            float4 p0 = w4s[b * 272 + 32 * 8 + dq];
            float4 p1 = w4s[b * 272 + 33 * 8 + dq];
            float a = dot4(Rs4[32 * 128 + rho * 8 + dq], p0) -
                      dot4(Rd4[32 * 128 + rho * 8 + dq], p1);
            a += __shfl_xor_sync(0xffffffffu, a, 2);
            a += __shfl_xor_sync(0xffffffffu, a, 4);
            a += __shfl_xor_sync(0xffffffffu, a, 8);
            if ((t & 14) == 0) re_sm[b * 528 + 32 * 16 + rho] = a;
        }
        __syncthreads();
        float4 acc = z4;
        const float* reb = re_sm + b * 528;
        const float4* rsc = Rs4 + (m + 1) * 128 + dq;
        const float4* rdc = Rd4 + m * 128 + dq;
#pragma unroll
        for (int rho = 0; rho < 16; rho++) {
            float wv = reb[(m + 1) * 16 + rho];
            float4 rv = rsc[rho * 8];
            acc.x = fmaf(rv.x, wv, acc.x);
            acc.y = fmaf(rv.y, wv, acc.y);
            acc.z = fmaf(rv.z, wv, acc.z);
            acc.w = fmaf(rv.w, wv, acc.w);
        }
#pragma unroll
        for (int rho = 0; rho < 16; rho++) {
            float wv = reb[m * 16 + rho];
            float4 rv = rdc[rho * 8];
            acc.x = fmaf(-rv.x, wv, acc.x);
            acc.y = fmaf(-rv.y, wv, acc.y);
            acc.z = fmaf(-rv.z, wv, acc.z);
            acc.w = fmaf(-rv.w, wv, acc.w);
        }
        q4.x = fmaf(LAMf, acc.x, w4.x);
        q4.y = fmaf(LAMf, acc.y, w4.y);
        q4.z = fmaf(LAMf, acc.z, w4.z);
        q4.w = fmaf(LAMf, acc.w, w4.w);
    };

    auto reduce2_arrive = [&](float vA, float vB, int par) {
#pragma unroll
        for (int o = 2; o <= 16; o <<= 1) {
            vA += __shfl_xor_sync(0xffffffffu, vA, o);
            vB += __shfl_xor_sync(0xffffffffu, vB, o);
        }
        if (l < 2) { redA[l * 16 + wp] = vA; redB[l * 16 + wp] = vB; }
        __syncthreads();
        if (wp == 0) {
            int row = l >> 3, col = l & 7;
            const float* arr = (row < 2) ? redA : redB;
            int bb2 = row & 1;
            float v2 = arr[bb2 * 16 + col] + arr[bb2 * 16 + col + 8];
            v2 += __shfl_xor_sync(0xffffffffu, v2, 1);
            v2 += __shfl_xor_sync(0xffffffffu, v2, 2);
            v2 += __shfl_xor_sync(0xffffffffu, v2, 4);
            if (col == 0) {
#pragma unroll
                for (int rr = 0; rr < 8; rr++) {
                    float* rem = (float*)cl.map_shared_rank((void*)slots, rr);
                    rem[par * 32 + row * 8 + s] = v2;
                }
            }
        }
        CLUSTER_ARRIVE();
    };

    auto fetch_halo = [&]() {
        if (t < 16) {
            if (s > 0) {
                const float4* rem = (const float4*)cl.map_shared_rank((void*)(smf + OFF_W), s - 1);
                w4s[b * 272 + dq] = rem[b * 272 + 32 * 8 + dq];
            }
        } else if (t < 32) {
            if (s < 7) {
                const float4* rem = (const float4*)cl.map_shared_rank((void*)(smf + OFF_W), s + 1);
                w4s[b * 272 + 33 * 8 + dq] = rem[b * 272 + 8 + dq];
            }
        }
    };

    // ---- init: x=c0; r=c0-Ac0; w=Ar ----
    w4 = w4s[b * 272 + (m + 1) * 8 + dq];
    matvec(0);
    x4 = w4;
    r4 = make_float4(x4.x - q4.x, x4.y - q4.y, x4.z - q4.z, x4.w - q4.w);
    __syncthreads();
    w4s[b * 272 + (m + 1) * 8 + dq] = r4;
    w4 = r4;
    CLUSTER_ARRIVE(); CLUSTER_WAIT();
    fetch_halo();
    // close the fetch-vs-overwrite race: everyone's halo read completes
    // before anyone's second matvec overwrites w4s[own]
    CLUSTER_ARRIVE(); CLUSTER_WAIT();
    __syncthreads();
    matvec(0);
    w4 = q4;
    __syncthreads();
    w4s[b * 272 + (m + 1) * 8 + dq] = w4;
    CLUSTER_ARRIVE(); CLUSTER_WAIT();
    fetch_halo();
    // fetch here is safe: peer's next w4s[own] write is gated on our
    // ARRIVE in iteration 0's reduce2_arrive (below)

    // ---- main loop ----
    for (int it = 0; it < CG_ITERS; it++) {
        int par = it & 1;
        reduce2_arrive(dot4(r4, r4), dot4(w4, r4), par);  // gamma, delta
        matvec(it);
        CLUSTER_WAIT();
        float bt[2], al[2];
#pragma unroll
        for (int bb = 0; bb < 2; bb++) {
            float gm = 0.f, dl = 0.f;
#pragma unroll
            for (int rr = 0; rr < 8; rr++) {
                gm += slots[par * 32 + bb * 8 + rr];
                dl += slots[par * 32 + (2 + bb) * 8 + rr];
            }
            if (it == 0) {
                bt[bb] = 0.f;
                al[bb] = gm / (dl + 1e-12f);
            } else {
                float beta = gm / (g_old[bb] + 1e-12f);
                bt[bb] = beta;
                al[bb] = gm / (dl - beta * gm / a_old[bb] + 1e-12f);
            }
            g_old[bb] = gm;
            a_old[bb] = al[bb];
        }
        float be = bt[b], a_ = al[b];
        zv4.x = fmaf(be, zv4.x, q4.x); zv4.y = fmaf(be, zv4.y, q4.y);
        zv4.z = fmaf(be, zv4.z, q4.z); zv4.w = fmaf(be, zv4.w, q4.w);
        s4.x = fmaf(be, s4.x, w4.x); s4.y = fmaf(be, s4.y, w4.y);
        s4.z = fmaf(be, s4.z, w4.z); s4.w = fmaf(be, s4.w, w4.w);
        p4.x = fmaf(be, p4.x, r4.x); p4.y = fmaf(be, p4.y, r4.y);
        p4.z = fmaf(be, p4.z, r4.z); p4.w = fmaf(be, p4.w, r4.w);
        x4.x = fmaf(a_, p4.x, x4.x); x4.y = fmaf(a_, p4.y, x4.y);
        x4.z = fmaf(a_, p4.z, x4.z); x4.w = fmaf(a_, p4.w, x4.w);
        r4.x = fmaf(-a_, s4.x, r4.x); r4.y = fmaf(-a_, s4.y, r4.y);
        r4.z = fmaf(-a_, s4.z, r4.z); r4.w = fmaf(-a_, s4.w, r4.w);
        w4.x = fmaf(-a_, zv4.x, w4.x); w4.y = fmaf(-a_, zv4.y, w4.y);
        w4.z = fmaf(-a_, zv4.z, w4.z); w4.w = fmaf(-a_, zv4.w, w4.w);
        w4s[b * 272 + (m + 1) * 8 + dq] = w4;
        // P2P halo push (double-buffered by parity); skip last iter (unused,
        // avoids dangling remote arrives at exit + balances mbar phases)
        if (it < CG_ITERS - 1) {
            if (t < 16) {
                if (s > 0) {
                    float4* rem = (float4*)cl.map_shared_rank((void*)(smf + OFF_STGR), s - 1);
                    rem[par * 16 + b * 8 + dq] = w4;
                }
                __syncwarp(0x0000FFFFu);
                if (t == 0 && s > 0) mbar_arrive_remote(mbarR, (unsigned)(s - 1));
            } else if (t >= 496) {
                if (s < 7) {
                    float4* rem = (float4*)cl.map_shared_rank((void*)(smf + OFF_STGL), s + 1);
                    rem[par * 16 + b * 8 + dq] = w4;
                }
                __syncwarp(0xFFFF0000u);
                if (t == 496 && s < 7) mbar_arrive_remote(mbarL, (unsigned)(s + 1));
            }
        }
    }

    int gm = s * 32 + m;
    int batch = c * 2 + b;
    ((float4*)g_cs)[(batch * Mn + gm) * 8 + dq] = x4;
    ((float4*)out_c)[(batch * Mn + gm) * 8 + dq] = x4;
}

// ---------------- decode: 1024 blocks, 16 q x 8 batches ----------------
__global__ __launch_bounds__(128) void k_decode(const float* __restrict__ phi,
                                                const float* __restrict__ w,
                                                float* __restrict__ out_s) {
    __shared__ float csm[3][Bn][Dn];
    int blk = blockIdx.x;
    int mlo = (blk >> 2) - 1;
    int t = threadIdx.x;
    for (int i = t; i < 3 * Bn * Dn; i += 128) {
        int mi = i >> 8, b = (i >> 5) & 7, d = i & 31;
        int mm = mlo + mi;
        csm[mi][b][d] = (mm >= 0 && mm < Mn) ? g_cs[(b * Mn + mm) * Dn + d] : 0.f;
    }
    __syncthreads();
    int b = t >> 4;
    int q = blk * 16 + (t & 15);
    float acc = 0.f;
#pragma unroll
    for (int kk = 0; kk < 3; kk++) {
        int mm = mlo + kk;
        bool valid = (mm >= 0) && (mm < Mn);
        int mc = valid ? mm : 0;
        float wv = valid ? __ldg(&w[(size_t)mc * Qn + q]) : 0.f;
        const float4* ph = (const float4*)(phi + ((size_t)mc * Qn + q) * Dn);
        const float4* cc = (const float4*)&csm[kk][b][0];
        float d0 = 0.f;
#pragma unroll
        for (int j = 0; j < 8; j++) d0 += dot4(__ldg(&ph[j]), cc[j]);
        acc = fmaf(wv, d0, acc);
    }
    out_s[b * Qn + q] = acc;
}

// ---------------- launch ----------------
extern "C" void kernel_launch(void* const* d_in, const int* in_sizes, int n_in,
                              void* d_out, int out_size) {
    const float* xs = (const float*)d_in[0];
    const float* us = (const float*)d_in[1];
    const float* phi_q = (const float*)d_in[2];
    const float* w = (const float*)d_in[3];
    const float* centers = (const float*)d_in[4];
    const float* R_src = (const float*)d_in[5];
    const float* R_dst = (const float*)d_in[6];
    const float* W1 = (const float*)d_in[7];
    const float* b1 = (const float*)d_in[8];
    const float* W2 = (const float*)d_in[9];
    const float* b2 = (const float*)d_in[10];
    const float* W3 = (const float*)d_in[11];
    const float* b3 = (const float*)d_in[12];
    const float* Wg1 = (const float*)d_in[13];
    const float* bg1 = (const float*)d_in[14];
    const float* Wg2 = (const float*)d_in[15];
    const float* bg2 = (const float*)d_in[16];
    const int* idx = (const int*)d_in[17];

    float* out = (float*)d_out;
    float* out_s = out;
    float* out_c0 = out + Bn * Qn;
    float* out_c = out + Bn * Qn + Bn * Mn * Dn;

    cudaFuncSetAttribute(k_cg, cudaFuncAttributeMaxDynamicSharedMemorySize,
                         CG_SM_FLOATS * (int)sizeof(float));

    k_g<<<Bn, 256>>>(xs, us, Wg1, bg1, Wg2, bg2);
    k_encode<<<512, 256>>>(xs, us, centers, W1, b1, W2, b2, W3, b3, idx, out_c0);
    k_cg<<<32, 512, CG_SM_FLOATS * sizeof(float)>>>(R_src, R_dst, out_c);
    k_decode<<<1024, 128>>>(phi_q, w, out_s);
}

// round 17
// speedup vs baseline: 1.1073x; 1.1073x over previous
#include <cuda_runtime.h>
#include <cooperative_groups.h>
namespace cg = cooperative_groups;

#define Bn 8
#define Nn 2048
#define Mn 256
#define Qn 16384
#define Dn 32
#define Kn 16
#define Hn 64
#define LAMf 5.0f
#define CG_ITERS 20

#define CLUSTER_ARRIVE() asm volatile("barrier.cluster.arrive.aligned;" ::: "memory")
#define CLUSTER_WAIT() asm volatile("barrier.cluster.wait.aligned;" ::: "memory")

__device__ float g_gvec[Bn * Dn];
__device__ float g_c0s[Bn * Mn * Dn];
__device__ float g_cs[Bn * Mn * Dn];

__device__ __forceinline__ float dot4(float4 a, float4 b) {
    return a.x * b.x + a.y * b.y + a.z * b.z + a.w * b.w;
}
__device__ __forceinline__ unsigned smem_u32(const void* p) {
    return (unsigned)__cvta_generic_to_shared(p);
}
__device__ __forceinline__ void mbar_init(unsigned a, unsigned c) {
    asm volatile("mbarrier.init.shared.b64 [%0], %1;" ::"r"(a), "r"(c) : "memory");
}
__device__ __forceinline__ void mbar_arrive_remote(unsigned local_addr, unsigned rank) {
    asm volatile(
        "{\n\t.reg .b32 ra;\n\t"
        "mapa.shared::cluster.u32 ra, %0, %1;\n\t"
        "mbarrier.arrive.release.cluster.shared::cluster.b64 _, [ra];\n\t}" ::"r"(local_addr),
        "r"(rank)
        : "memory");
}
__device__ __forceinline__ void mbar_wait(unsigned a, unsigned parity) {
    asm volatile(
        "{\n\t.reg .pred P;\n\tWL_%=:\n\t"
        "mbarrier.try_wait.parity.acquire.cluster.shared::cta.b64 P, [%0], %1;\n\t"
        "@P bra WD_%=;\n\tbra WL_%=;\n\tWD_%=:\n\t}" ::"r"(a),
        "r"(parity)
        : "memory");
}

// ---------------- k_g ----------------
__global__ __launch_bounds__(256) void k_g(const float* __restrict__ xs,
                                           const float* __restrict__ us,
                                           const float* __restrict__ Wg1,
                                           const float* __restrict__ bg1,
                                           const float* __restrict__ Wg2,
                                           const float* __restrict__ bg2) {
    __shared__ float part[256];
    __shared__ float gmean[Hn];
    int b = blockIdx.x, t = threadIdx.x;
    int h = t & 63, grp = t >> 6;
    float w0 = Wg1[h], w1 = Wg1[Hn + h], bb = bg1[h];
    float acc = 0.f;
    for (int n = grp; n < Nn; n += 4) {
        float v = fmaf(xs[b * Nn + n], w0, fmaf(us[b * Nn + n], w1, bb));
        acc += fmaxf(v, 0.f);
    }
    part[t] = acc;
    __syncthreads();
    if (t < Hn)
        gmean[t] = (part[t] + part[t + 64] + part[t + 128] + part[t + 192]) * (1.0f / (float)Nn);
    __syncthreads();
    if (t < Dn) {
        float a = bg2[t];
#pragma unroll
        for (int hh = 0; hh < Hn; hh++) a = fmaf(gmean[hh], Wg2[hh * Dn + t], a);
        g_gvec[b * Dn + t] = a;
    }
}

// ---------------- encoder (4 m / block) ----------------
__global__ __launch_bounds__(256) void k_encode(const float* __restrict__ xs,
                                                const float* __restrict__ us,
                                                const float* __restrict__ centers,
                                                const float* __restrict__ W1,
                                                const float* __restrict__ b1,
                                                const float* __restrict__ W2,
                                                const float* __restrict__ b2,
                                                const float* __restrict__ W3,
                                                const float* __restrict__ b3,
                                                const int* __restrict__ idx,
                                                float* __restrict__ out_c0) {
    __shared__ float W2s[Hn * Hn];
    __shared__ float h1[4][Kn][Hn];
    __shared__ float sx[4][Kn], su[4][Kn];
    __shared__ float hm[4][Hn];
    int blk = blockIdx.x;
    int b = blk >> 6, mbase = (blk & 63) << 2;
    int t = threadIdx.x, gr = t >> 6, h = t & 63;

    for (int i = t; i < Hn * Hn; i += 256) W2s[i] = W2[i];
    if (t < 64) {
        int gr2 = t >> 4, k = t & 15;
        int id = idx[(mbase + gr2) * Kn + k];
        sx[gr2][k] = xs[b * Nn + id];
        su[gr2][k] = us[b * Nn + id];
    }
    __syncthreads();
    int m = mbase + gr;
    const float invR = (float)Mn / 1.5f;
    float w1a = W1[h], w1b = W1[Hn + h], bb1 = b1[h];
    float cm = centers[m];
#pragma unroll
    for (int k = 0; k < Kn; k++) {
        float rel = (sx[gr][k] - cm) * invR;
        h1[gr][k][h] = fmaxf(fmaf(rel, w1a, fmaf(su[gr][k], w1b, bb1)), 0.f);
    }
    __syncthreads();
    float bb2 = b2[h];
    float accv[Kn];
#pragma unroll
    for (int k = 0; k < Kn; k++) accv[k] = bb2;
#pragma unroll
    for (int hh = 0; hh < Hn; hh += 4) {
        float wa = W2s[(hh + 0) * Hn + h], wb = W2s[(hh + 1) * Hn + h];
        float wc = W2s[(hh + 2) * Hn + h], wd = W2s[(hh + 3) * Hn + h];
#pragma unroll
        for (int k = 0; k < Kn; k++) {
            float4 hv = *(const float4*)&h1[gr][k][hh];
            accv[k] = fmaf(hv.x, wa, accv[k]);
            accv[k] = fmaf(hv.y, wb, accv[k]);
            accv[k] = fmaf(hv.z, wc, accv[k]);
            accv[k] = fmaf(hv.w, wd, accv[k]);
        }
    }
    float ssum = 0.f;
#pragma unroll
    for (int k = 0; k < Kn; k++) ssum += fmaxf(accv[k], 0.f);
    hm[gr][h] = ssum * (1.0f / (float)Kn);
    __syncthreads();
    if (h < Dn) {
        float a = b3[h];
#pragma unroll
        for (int hh = 0; hh < Hn; hh++) a = fmaf(hm[gr][hh], W3[hh * Dn + h], a);
        a += g_gvec[b * Dn + h];
        int gi = (b * Mn + m) * Dn + h;
        g_c0s[gi] = a;
        out_c0[gi] = a;
    }
}

// ==================== pipelined CG: 8 clusters x 8 CTAs, 1 batch, rh-split matvec ========
// t = m*16 + rh*8 + dq  (m = node 0..31, rh = rho-half, dq = d-quad)
#define OFF_RS 0
#define OFF_RD 16896
#define OFF_W 33792    // [34][32] (slots)
#define OFF_TA 34880   // [33][16]
#define OFF_TB 35408   // [33][16]
#define OFF_REDA 35936 // [16]
#define OFF_REDB 35952 // [16]
#define OFF_SLOT 35968 // [2 par][2 val][8 rank]
#define OFF_STGL 36000 // [2 par][8 float4]
#define OFF_STGR 36064
#define OFF_MBAR 36128 // 2 x u64
#define CG_SM_FLOATS 36132

__global__ void __cluster_dims__(8, 1, 1) __launch_bounds__(512, 1)
    k_cg(const float* __restrict__ Rsrc, const float* __restrict__ Rdst,
         float* __restrict__ out_c) {
    extern __shared__ float smf[];
    float4* Rs4 = (float4*)(smf + OFF_RS);
    float4* Rd4 = (float4*)(smf + OFF_RD);
    float4* w4s = (float4*)(smf + OFF_W);
    float* tA = smf + OFF_TA;
    float* tB = smf + OFF_TB;
    float* redA = smf + OFF_REDA;
    float* redB = smf + OFF_REDB;
    float* slots = smf + OFF_SLOT;
    float4* stgL = (float4*)(smf + OFF_STGL);
    float4* stgR = (float4*)(smf + OFF_STGR);

    cg::cluster_group cl = cg::this_cluster();
    const int t = threadIdx.x;
    const int l = t & 31, wp = t >> 5;
    const int c = blockIdx.x >> 3;  // batch
    const int s = blockIdx.x & 7;   // rank: nodes [32s, 32s+32)
    const int m = t >> 4;
    const int rh = (t >> 3) & 1;
    const int dq = t & 7;
    const float4 z4 = make_float4(0.f, 0.f, 0.f, 0.f);
    const unsigned mbarL = smem_u32(smf + OFF_MBAR);
    const unsigned mbarR = mbarL + 8;

    if (t == 0) { mbar_init(mbarL, 1); mbar_init(mbarR, 1); }

    // ---- prologue: R slice (33 local edges, invalid zeroed) + w = c0 on ext slots ----
    const float4* Rsg = (const float4*)Rsrc;
    const float4* Rdg = (const float4*)Rdst;
    for (int i4 = t; i4 < 33 * 128; i4 += 512) {
        int le = i4 >> 7, rem = i4 & 127;
        int ge = s * 32 - 1 + le;
        bool ok = (ge >= 0) && (ge < Mn - 1);
        Rs4[i4] = ok ? Rsg[ge * 128 + rem] : z4;
        Rd4[i4] = ok ? Rdg[ge * 128 + rem] : z4;
    }
    const float4* c0g = (const float4*)g_c0s;
    if (t < 272) {
        int slot = t >> 3, j = t & 7;
        int gm = s * 32 - 1 + slot;
        w4s[t] = (gm >= 0 && gm < Mn) ? c0g[(c * Mn + gm) * 8 + j] : z4;
    }
    __syncthreads();

    float4 x4, r4, w4, q4, p4 = z4, s4 = z4, zv4 = z4;
    float g_old = 0.f, a_old = 1.f;

    // ---- matvec: q4 = A w ----
    auto matvec = [&](int it) {
        if (it > 0) {
            unsigned par2 = (unsigned)((it - 1) & 1);
            if (t < 8) {
                if (s > 0) { mbar_wait(mbarL, par2); w4s[t] = stgL[par2 * 8 + t]; }
            } else if (t < 16) {
                int j = t - 8;
                if (s < 7) { mbar_wait(mbarR, par2); w4s[33 * 8 + j] = stgR[par2 * 8 + j]; }
            }
        }
        __syncthreads();
        // phase A: team m computes t1[m+1] = Rs[m+1].p[own], t2[m] = Rd[m].p[own]
        {
            const float4 pown = w4;
            const int rbase = rh * 8;
            const float4* rsp = Rs4 + (m + 1) * 128 + dq;
            const float4* rdp = Rd4 + m * 128 + dq;
#pragma unroll
            for (int rr = 0; rr < 8; rr++) {
                int rho = rbase + rr;
                float a1 = dot4(rsp[rho * 8], pown);
                float a2 = dot4(rdp[rho * 8], pown);
                a1 += __shfl_xor_sync(0xffffffffu, a1, 1);
                a2 += __shfl_xor_sync(0xffffffffu, a2, 1);
                a1 += __shfl_xor_sync(0xffffffffu, a1, 2);
                a2 += __shfl_xor_sync(0xffffffffu, a2, 2);
                a1 += __shfl_xor_sync(0xffffffffu, a1, 4);
                a2 += __shfl_xor_sync(0xffffffffu, a2, 4);
                if (dq == 0) {
                    tA[(m + 1) * 16 + rho] = a1;
                    tB[m * 16 + rho] = a2;
                }
            }
            if (m == 0) {  // extra: t1[0] = Rs[0].p[slot0]  (warp0 lanes 0-15)
                float4 p0 = w4s[dq];
#pragma unroll
                for (int rr = 0; rr < 8; rr++) {
                    int rho = rbase + rr;
                    float a = dot4(Rs4[rho * 8 + dq], p0);
                    a += __shfl_xor_sync(0x0000FFFFu, a, 1);
                    a += __shfl_xor_sync(0x0000FFFFu, a, 2);
                    a += __shfl_xor_sync(0x0000FFFFu, a, 4);
                    if (dq == 0) tA[rho] = a;
                }
            }
            if (m == 31) {  // extra: t2[32] = Rd[32].p[slot33]  (warp15 lanes 16-31)
                float4 p33 = w4s[33 * 8 + dq];
#pragma unroll
                for (int rr = 0; rr < 8; rr++) {
                    int rho = rbase + rr;
                    float a = dot4(Rd4[32 * 128 + rho * 8 + dq], p33);
                    a += __shfl_xor_sync(0xFFFF0000u, a, 1);
                    a += __shfl_xor_sync(0xFFFF0000u, a, 2);
                    a += __shfl_xor_sync(0xFFFF0000u, a, 4);
                    if (dq == 0) tB[32 * 16 + rho] = a;
                }
            }
        }
        __syncthreads();
        // phase B: rh0 accumulates Rs[m+1]^T re[m+1], rh1 accumulates Rd[m]^T re[m]
        {
            const float4* matp = rh ? (Rd4 + m * 128 + dq) : (Rs4 + (m + 1) * 128 + dq);
            const int le = rh ? m : (m + 1);
            const float* ta = tA + le * 16;
            const float* tb = tB + le * 16;
            float4 acc = z4;
#pragma unroll
            for (int rho = 0; rho < 16; rho++) {
                float re = ta[rho] - tb[rho];
                float4 rv = matp[rho * 8];
                acc.x = fmaf(rv.x, re, acc.x);
                acc.y = fmaf(rv.y, re, acc.y);
                acc.z = fmaf(rv.z, re, acc.z);
                acc.w = fmaf(rv.w, re, acc.w);
            }
            float ox = __shfl_xor_sync(0xffffffffu, acc.x, 8);
            float oy = __shfl_xor_sync(0xffffffffu, acc.y, 8);
            float oz = __shfl_xor_sync(0xffffffffu, acc.z, 8);
            float ow = __shfl_xor_sync(0xffffffffu, acc.w, 8);
            float lam = rh ? -LAMf : LAMf;
            q4.x = fmaf(lam, acc.x - ox, w4.x);
            q4.y = fmaf(lam, acc.y - oy, w4.y);
            q4.z = fmaf(lam, acc.z - oz, w4.z);
            q4.w = fmaf(lam, acc.w - ow, w4.w);
        }
    };

    // ---- reduction: gamma = 0.5 r.r, delta = 0.5 w.r (0.5 for rh duplication), arrive ----
    auto reduce2_arrive = [&](int par) {
        float vA = 0.5f * dot4(r4, r4);
        float vB = 0.5f * dot4(w4, r4);
#pragma unroll
        for (int o = 1; o <= 16; o <<= 1) {
            vA += __shfl_xor_sync(0xffffffffu, vA, o);
            vB += __shfl_xor_sync(0xffffffffu, vB, o);
        }
        if (l == 0) { redA[wp] = vA; redB[wp] = vB; }
        __syncthreads();
        if (wp == 0) {
            float g = 0.f, d = 0.f;
#pragma unroll
            for (int rr = 0; rr < 16; rr++) { g += redA[rr]; d += redB[rr]; }
            if (l < 8) {
                float* rem = (float*)cl.map_shared_rank((void*)slots, l);
                rem[par * 16 + s] = g;
            } else if (l < 16) {
                float* rem = (float*)cl.map_shared_rank((void*)slots, l - 8);
                rem[par * 16 + 8 + s] = d;
            }
        }
        CLUSTER_ARRIVE();
    };

    auto fetch_halo = [&]() {
        if (t < 8) {
            if (s > 0) {
                const float4* rem = (const float4*)cl.map_shared_rank((void*)(smf + OFF_W), s - 1);
                w4s[t] = rem[32 * 8 + t];
            }
        } else if (t < 16) {
            int j = t - 8;
            if (s < 7) {
                const float4* rem = (const float4*)cl.map_shared_rank((void*)(smf + OFF_W), s + 1);
                w4s[33 * 8 + j] = rem[8 + j];
            }
        }
    };

    // ---- init: x=c0; r=c0-Ac0; w=Ar ----
    w4 = w4s[(m + 1) * 8 + dq];
    matvec(0);
    x4 = w4;
    r4 = make_float4(x4.x - q4.x, x4.y - q4.y, x4.z - q4.z, x4.w - q4.w);
    __syncthreads();
    if (rh == 0) w4s[(m + 1) * 8 + dq] = r4;
    w4 = r4;
    CLUSTER_ARRIVE(); CLUSTER_WAIT();
    fetch_halo();
    CLUSTER_ARRIVE(); CLUSTER_WAIT();  // halo reads done before next overwrite
    __syncthreads();
    matvec(0);
    w4 = q4;
    __syncthreads();
    if (rh == 0) w4s[(m + 1) * 8 + dq] = w4;
    CLUSTER_ARRIVE(); CLUSTER_WAIT();
    fetch_halo();
    // next overwrite of w4s gated on iteration-0 reduce's ARRIVE

    // ---- main loop (Ghysels-Vanroose pipelined CG) ----
    for (int it = 0; it < CG_ITERS; it++) {
        int par = it & 1;
        reduce2_arrive(par);
        matvec(it);
        CLUSTER_WAIT();
        float gm_ = 0.f, dl = 0.f;
#pragma unroll
        for (int rr = 0; rr < 8; rr++) {
            gm_ += slots[par * 16 + rr];
            dl += slots[par * 16 + 8 + rr];
        }
        float beta, alpha;
        if (it == 0) {
            beta = 0.f;
            alpha = gm_ / (dl + 1e-12f);
        } else {
            beta = gm_ / (g_old + 1e-12f);
            alpha = gm_ / (dl - beta * gm_ / a_old + 1e-12f);
        }
        g_old = gm_;
        a_old = alpha;

        zv4.x = fmaf(beta, zv4.x, q4.x); zv4.y = fmaf(beta, zv4.y, q4.y);
        zv4.z = fmaf(beta, zv4.z, q4.z); zv4.w = fmaf(beta, zv4.w, q4.w);
        s4.x = fmaf(beta, s4.x, w4.x); s4.y = fmaf(beta, s4.y, w4.y);
        s4.z = fmaf(beta, s4.z, w4.z); s4.w = fmaf(beta, s4.w, w4.w);
        p4.x = fmaf(beta, p4.x, r4.x); p4.y = fmaf(beta, p4.y, r4.y);
        p4.z = fmaf(beta, p4.z, r4.z); p4.w = fmaf(beta, p4.w, r4.w);
        x4.x = fmaf(alpha, p4.x, x4.x); x4.y = fmaf(alpha, p4.y, x4.y);
        x4.z = fmaf(alpha, p4.z, x4.z); x4.w = fmaf(alpha, p4.w, x4.w);
        r4.x = fmaf(-alpha, s4.x, r4.x); r4.y = fmaf(-alpha, s4.y, r4.y);
        r4.z = fmaf(-alpha, s4.z, r4.z); r4.w = fmaf(-alpha, s4.w, r4.w);
        w4.x = fmaf(-alpha, zv4.x, w4.x); w4.y = fmaf(-alpha, zv4.y, w4.y);
        w4.z = fmaf(-alpha, zv4.z, w4.z); w4.w = fmaf(-alpha, zv4.w, w4.w);
        if (rh == 0) w4s[(m + 1) * 8 + dq] = w4;

        // P2P halo push (parity double-buffered); last iter skipped
        if (it < CG_ITERS - 1) {
            if (t >= 496 && t < 504) {  // node 31, rh0 -> right neighbor's slot0
                if (s < 7) {
                    float4* rem = (float4*)cl.map_shared_rank((void*)(smf + OFF_STGL), s + 1);
                    rem[par * 8 + dq] = w4;
                }
                __syncwarp(0x00FF0000u);
                if (t == 496 && s < 7) mbar_arrive_remote(mbarL, (unsigned)(s + 1));
            } else if (t < 8) {  // node 0, rh0 -> left neighbor's slot33
                if (s > 0) {
                    float4* rem = (float4*)cl.map_shared_rank((void*)(smf + OFF_STGR), s - 1);
                    rem[par * 8 + dq] = w4;
                }
                __syncwarp(0x000000FFu);
                if (t == 0 && s > 0) mbar_arrive_remote(mbarR, (unsigned)(s - 1));
            }
        }
    }

    if (rh == 0) {
        int gm = s * 32 + m;
        ((float4*)g_cs)[(c * Mn + gm) * 8 + dq] = x4;
        ((float4*)out_c)[(c * Mn + gm) * 8 + dq] = x4;
    }
}

// ---------------- decode: 256 blocks x 128 thr, thread = (q, 4 batches) ----------------
__global__ __launch_bounds__(128) void k_decode(const float* __restrict__ phi,
                                                const float* __restrict__ w,
                                                float* __restrict__ out_s) {
    __shared__ float csm[3][Bn][Dn];
    int blk = blockIdx.x;  // 64 q per block, all with q/64 == blk
    int t = threadIdx.x;
    for (int i = t; i < 3 * Bn * Dn; i += 128) {
        int mi = i >> 8, b = (i >> 5) & 7, d = i & 31;
        int mm = blk - 1 + mi;
        csm[mi][b][d] = (mm >= 0 && mm < Mn) ? g_cs[(b * Mn + mm) * Dn + d] : 0.f;
    }
    __syncthreads();
    int qi = t & 63, bh = t >> 6;  // bh = 0/1 -> batches 4bh..4bh+3
    int q = blk * 64 + qi;
    float a0 = 0.f, a1 = 0.f, a2 = 0.f, a3 = 0.f;
#pragma unroll
    for (int kk = 0; kk < 3; kk++) {
        int mm = blk - 1 + kk;
        bool valid = (mm >= 0) && (mm < Mn);
        int mc = valid ? mm : 0;
        float wv = valid ? __ldg(&w[(size_t)mc * Qn + q]) : 0.f;
        const float4* ph = (const float4*)(phi + ((size_t)mc * Qn + q) * Dn);
        const float4* c0 = (const float4*)&csm[kk][bh * 4 + 0][0];
        const float4* c1 = (const float4*)&csm[kk][bh * 4 + 1][0];
        const float4* c2 = (const float4*)&csm[kk][bh * 4 + 2][0];
        const float4* c3 = (const float4*)&csm[kk][bh * 4 + 3][0];
        float d0 = 0.f, d1 = 0.f, d2 = 0.f, d3 = 0.f;
#pragma unroll
        for (int j = 0; j < 8; j++) {
            float4 pv = __ldg(&ph[j]);
            d0 += dot4(pv, c0[j]);
            d1 += dot4(pv, c1[j]);
            d2 += dot4(pv, c2[j]);
            d3 += dot4(pv, c3[j]);
        }
        a0 = fmaf(wv, d0, a0);
        a1 = fmaf(wv, d1, a1);
        a2 = fmaf(wv, d2, a2);
        a3 = fmaf(wv, d3, a3);
    }
    out_s[(bh * 4 + 0) * Qn + q] = a0;
    out_s[(bh * 4 + 1) * Qn + q] = a1;
    out_s[(bh * 4 + 2) * Qn + q] = a2;
    out_s[(bh * 4 + 3) * Qn + q] = a3;
}

// ---------------- launch ----------------
extern "C" void kernel_launch(void* const* d_in, const int* in_sizes, int n_in,
                              void* d_out, int out_size) {
    const float* xs = (const float*)d_in[0];
    const float* us = (const float*)d_in[1];
    const float* phi_q = (const float*)d_in[2];
    const float* w = (const float*)d_in[3];
    const float* centers = (const float*)d_in[4];
    const float* R_src = (const float*)d_in[5];
    const float* R_dst = (const float*)d_in[6];
    const float* W1 = (const float*)d_in[7];
    const float* b1 = (const float*)d_in[8];
    const float* W2 = (const float*)d_in[9];
    const float* b2 = (const float*)d_in[10];
    const float* W3 = (const float*)d_in[11];
    const float* b3 = (const float*)d_in[12];
    const float* Wg1 = (const float*)d_in[13];
    const float* bg1 = (const float*)d_in[14];
    const float* Wg2 = (const float*)d_in[15];
    const float* bg2 = (const float*)d_in[16];
    const int* idx = (const int*)d_in[17];

    float* out = (float*)d_out;
    float* out_s = out;
    float* out_c0 = out + Bn * Qn;
    float* out_c = out + Bn * Qn + Bn * Mn * Dn;

    cudaFuncSetAttribute(k_cg, cudaFuncAttributeMaxDynamicSharedMemorySize,
                         CG_SM_FLOATS * (int)sizeof(float));

    k_g<<<Bn, 256>>>(xs, us, Wg1, bg1, Wg2, bg2);
    k_encode<<<512, 256>>>(xs, us, centers, W1, b1, W2, b2, W3, b3, idx, out_c0);
    k_cg<<<64, 512, CG_SM_FLOATS * sizeof(float)>>>(R_src, R_dst, out_c);
    k_decode<<<256, 128>>>(phi_q, w, out_s);
}